// round 2
// baseline (speedup 1.0000x reference)
#include <cuda_runtime.h>
#include <cuda_bf16.h>
#include <math.h>
#include <stdint.h>

#define HID   128
#define KNN_K 10
#define NPT   4096
#define BB    4
#define NPTS  (BB*NPT)           // 16384
#define NC    (NPTS*3)           // 49152 columns
#define RESO_ 64
#define NCELL (RESO_*RESO_)      // 4096
#define EPSF  1e-6f
#define TN    192                // gemm column tile

// ---------------- static device scratch ----------------
__device__ __align__(128) float4 g_p4[NPTS];
__device__ __align__(128) int    g_idx[NPTS*KNN_K];
__device__ __align__(128) float  g_cnt[3*BB*NCELL];
__device__ __align__(128) float  g_z0[2*NC];
__device__ __align__(128) float  g_WfcT[HID*HID];
__device__ __align__(128) float  g_WdTs[10*HID*HID];
__device__ __align__(128) float  g_WTs [10*HID*HID];
__device__ __align__(128) float  g_Ws1fT[128*64];
__device__ __align__(128) float  g_Ws1dT[128*64];
__device__ __align__(128) float  g_Ws2fT[64*32];
__device__ __align__(128) float  g_Ws2dT[64*32];
__device__ __align__(128) float  g_WslinT[32*2];
__device__ __align__(128) float  g_bufA[HID*NC];
__device__ __align__(128) float  g_bufB[HID*NC];

// ---------------- prep: pack points + squared norm ----------------
__global__ void prep_points(const float* __restrict__ p) {
    int i = blockIdx.x*blockDim.x + threadIdx.x;
    if (i < NPTS) {
        float x = p[i*3+0], y = p[i*3+1], z = p[i*3+2];
        g_p4[i] = make_float4(x, y, z, x*x + y*y + z*z);
    }
}

// ---------------- transpose all weight matrices: dst[i*O+o] = src[o*I+i] ----------------
__global__ void transpose_all(const float* __restrict__ Wfc,
                              const float* __restrict__ Wd0s, const float* __restrict__ W0s,
                              const float* __restrict__ Wd1s, const float* __restrict__ W1s,
                              const float* __restrict__ Ws1f, const float* __restrict__ Ws1d,
                              const float* __restrict__ Ws2f, const float* __restrict__ Ws2d,
                              const float* __restrict__ Wslin) {
    int m = blockIdx.y;
    const float* src; float* dst; int O, I;
    if (m < 10)      { int i = m >> 1; src = (m & 1) ? (Wd1s + i*16384) : (Wd0s + i*16384);
                       dst = g_WdTs + m*16384; O = 128; I = 128; }
    else if (m < 20) { int h = m - 10; int i = h >> 1; src = (h & 1) ? (W1s + i*16384) : (W0s + i*16384);
                       dst = g_WTs + h*16384; O = 128; I = 128; }
    else if (m == 20){ src = Wfc;   dst = g_WfcT;  O = 128; I = 128; }
    else if (m == 21){ src = Ws1f;  dst = g_Ws1fT; O = 64;  I = 128; }
    else if (m == 22){ src = Ws1d;  dst = g_Ws1dT; O = 64;  I = 128; }
    else if (m == 23){ src = Ws2f;  dst = g_Ws2fT; O = 32;  I = 64; }
    else if (m == 24){ src = Ws2d;  dst = g_Ws2dT; O = 32;  I = 64; }
    else             { src = Wslin; dst = g_WslinT;O = 2;   I = 32; }
    int n = O * I;
    for (int e = blockIdx.x*blockDim.x + threadIdx.x; e < n; e += gridDim.x*blockDim.x) {
        int o = e / I, i = e % I;
        dst[i*O + o] = src[e];
    }
}

// ---------------- brute-force KNN (top-10 of 2*dot - |x|^2 - |y|^2) ----------------
__global__ void knn_kernel() {
    __shared__ float4 cand[128];
    int pt = blockIdx.x*128 + threadIdx.x;       // 4096/128 blocks per batch -> aligned
    int base = (pt >> 12) << 12;
    float4 me = g_p4[pt];
    float v[KNN_K]; int id[KNN_K];
    #pragma unroll
    for (int i = 0; i < KNN_K; i++) { v[i] = -INFINITY; id[i] = 0; }
    for (int t = 0; t < NPT; t += 128) {
        __syncthreads();
        cand[threadIdx.x] = g_p4[base + t + threadIdx.x];
        __syncthreads();
        #pragma unroll 4
        for (int j = 0; j < 128; j++) {
            float4 c = cand[j];
            float nd = 2.0f*(me.x*c.x + me.y*c.y + me.z*c.z) - me.w - c.w;
            if (nd > v[KNN_K-1]) {
                v[KNN_K-1] = nd; id[KNN_K-1] = t + j;
                #pragma unroll
                for (int s = KNN_K-1; s > 0; s--) {
                    if (v[s] > v[s-1]) {
                        float tv = v[s]; v[s] = v[s-1]; v[s-1] = tv;
                        int ti = id[s]; id[s] = id[s-1]; id[s-1] = ti;
                    }
                }
            }
        }
    }
    #pragma unroll
    for (int i = 0; i < KNN_K; i++) g_idx[pt*KNN_K + i] = base + id[i];
}

// ---------------- edge features + first VN layer (slope 0) + mean over k ----------------
// out[o][col], col = pt*3 + coord ; 8 points per block, 1024 threads
__global__ __launch_bounds__(1024) void edge_vn(const float* __restrict__ Wf,
                                                const float* __restrict__ Wd,
                                                float* __restrict__ out) {
    __shared__ float fe[8][KNN_K][9];   // [q][j][i*3+c]: i0=neigh-x, i1=x, i2=cross(neigh,x)
    __shared__ float os[128*24];
    int tid = threadIdx.x;
    int q = tid >> 7, o = tid & 127;
    int p0 = blockIdx.x * 8;
    int pt = p0 + q;
    float4 xm = g_p4[pt];
    if (o < KNN_K) {
        float4 nb = g_p4[g_idx[pt*KNN_K + o]];
        fe[q][o][0] = nb.x - xm.x; fe[q][o][1] = nb.y - xm.y; fe[q][o][2] = nb.z - xm.z;
        fe[q][o][3] = xm.x;        fe[q][o][4] = xm.y;        fe[q][o][5] = xm.z;
        fe[q][o][6] = nb.y*xm.z - nb.z*xm.y;
        fe[q][o][7] = nb.z*xm.x - nb.x*xm.z;
        fe[q][o][8] = nb.x*xm.y - nb.y*xm.x;
    }
    __syncthreads();
    float wf0 = Wf[o*3], wf1 = Wf[o*3+1], wf2 = Wf[o*3+2];
    float wd0 = Wd[o*3], wd1 = Wd[o*3+1], wd2 = Wd[o*3+2];
    float a0 = 0.f, a1 = 0.f, a2 = 0.f;
    #pragma unroll
    for (int j = 0; j < KNN_K; j++) {
        const float* e = fe[q][j];
        float x0 = wf0*e[0] + wf1*e[3] + wf2*e[6];
        float x1 = wf0*e[1] + wf1*e[4] + wf2*e[7];
        float x2 = wf0*e[2] + wf1*e[5] + wf2*e[8];
        float d0 = wd0*e[0] + wd1*e[3] + wd2*e[6];
        float d1 = wd0*e[1] + wd1*e[4] + wd2*e[7];
        float d2 = wd0*e[2] + wd1*e[5] + wd2*e[8];
        float dot = x0*d0 + x1*d1 + x2*d2;
        if (dot < 0.f) {
            float s = dot / (d0*d0 + d1*d1 + d2*d2 + EPSF);
            x0 -= s*d0; x1 -= s*d1; x2 -= s*d2;
        }
        a0 += x0; a1 += x1; a2 += x2;
    }
    os[o*24 + q*3 + 0] = a0 / 10.0f;
    os[o*24 + q*3 + 1] = a1 / 10.0f;
    os[o*24 + q*3 + 2] = a2 / 10.0f;
    __syncthreads();
    for (int f = tid; f < 768; f += 1024) {
        int r = f / 6, c4 = f % 6;
        *(float4*)(out + r*NC + p0*3 + c4*4) = *(float4*)(os + r*24 + c4*4);
    }
}

// ---------------- fused half-step: Y = W * act(X, Wd*X) [+ resid] ----------------
// smem: Xs[128][192] + Ws[128][128] + Wds[128][128] -> 229376 bytes
template<bool ACT, bool RESID>
__global__ __launch_bounds__(256, 1) void gemm_hs(const float* __restrict__ X,
                                                  const float* __restrict__ WdT,
                                                  const float* __restrict__ WT,
                                                  const float* __restrict__ R,
                                                  float* __restrict__ Y) {
    extern __shared__ float sm[];
    float* Xs  = sm;                 // 128*192
    float* Ws  = sm + 128*TN;        // 128*128 [k][m]
    float* Wds = Ws + 128*128;       // 128*128 [k][m]
    const int tid  = threadIdx.x;
    const int col0 = blockIdx.x * TN;

    for (int f = tid; f < 6144; f += 256) {
        int r = f / 48, c4 = f % 48;
        *(float4*)(Xs + r*TN + c4*4) = *(const float4*)(X + r*NC + col0 + c4*4);
    }
    for (int f = tid; f < 4096; f += 256) {
        ((float4*)Ws)[f] = ((const float4*)WT)[f];
        if (ACT) ((float4*)Wds)[f] = ((const float4*)WdT)[f];
    }
    __syncthreads();

    const int rg = tid >> 4, cg = tid & 15;
    const int r0 = rg * 8, c0 = cg * 12;
    float acc[8][12];

    if (ACT) {
        #pragma unroll
        for (int i = 0; i < 8; i++)
            #pragma unroll
            for (int j = 0; j < 12; j++) acc[i][j] = 0.f;
        #pragma unroll 4
        for (int k = 0; k < 128; k++) {
            float4 wa = *(float4*)(Wds + k*128 + r0);
            float4 wb = *(float4*)(Wds + k*128 + r0 + 4);
            float4 xa = *(float4*)(Xs + k*TN + c0);
            float4 xb = *(float4*)(Xs + k*TN + c0 + 4);
            float4 xc = *(float4*)(Xs + k*TN + c0 + 8);
            float w[8]  = {wa.x,wa.y,wa.z,wa.w,wb.x,wb.y,wb.z,wb.w};
            float x[12] = {xa.x,xa.y,xa.z,xa.w,xb.x,xb.y,xb.z,xb.w,xc.x,xc.y,xc.z,xc.w};
            #pragma unroll
            for (int i = 0; i < 8; i++)
                #pragma unroll
                for (int j = 0; j < 12; j++) acc[i][j] += w[i]*x[j];
        }
        __syncthreads();
        // act (slope 0): overwrite Xs with A (thread-private positions only)
        #pragma unroll
        for (int i = 0; i < 8; i++) {
            float* row = Xs + (r0+i)*TN + c0;
            #pragma unroll
            for (int t3 = 0; t3 < 4; t3++) {
                float x0 = row[t3*3], x1 = row[t3*3+1], x2 = row[t3*3+2];
                float d0 = acc[i][t3*3], d1 = acc[i][t3*3+1], d2 = acc[i][t3*3+2];
                float dot = x0*d0 + x1*d1 + x2*d2;
                if (dot < 0.f) {
                    float s = dot / (d0*d0 + d1*d1 + d2*d2 + EPSF);
                    row[t3*3]   = x0 - s*d0;
                    row[t3*3+1] = x1 - s*d1;
                    row[t3*3+2] = x2 - s*d2;
                }
            }
        }
        __syncthreads();
    }

    #pragma unroll
    for (int i = 0; i < 8; i++)
        #pragma unroll
        for (int j = 0; j < 12; j++) acc[i][j] = 0.f;
    #pragma unroll 4
    for (int k = 0; k < 128; k++) {
        float4 wa = *(float4*)(Ws + k*128 + r0);
        float4 wb = *(float4*)(Ws + k*128 + r0 + 4);
        float4 xa = *(float4*)(Xs + k*TN + c0);
        float4 xb = *(float4*)(Xs + k*TN + c0 + 4);
        float4 xc = *(float4*)(Xs + k*TN + c0 + 8);
        float w[8]  = {wa.x,wa.y,wa.z,wa.w,wb.x,wb.y,wb.z,wb.w};
        float x[12] = {xa.x,xa.y,xa.z,xa.w,xb.x,xb.y,xb.z,xb.w,xc.x,xc.y,xc.z,xc.w};
        #pragma unroll
        for (int i = 0; i < 8; i++)
            #pragma unroll
            for (int j = 0; j < 12; j++) acc[i][j] += w[i]*x[j];
    }
    __syncthreads();
    #pragma unroll
    for (int i = 0; i < 8; i++)
        #pragma unroll
        for (int j = 0; j < 12; j++) Xs[(r0+i)*TN + c0 + j] = acc[i][j];
    __syncthreads();
    for (int f = tid; f < 6144; f += 256) {
        int r = f / 48, c4 = f % 48;
        float4 v = *(float4*)(Xs + r*TN + c4*4);
        if (RESID) {
            float4 rv = *(const float4*)(R + r*NC + col0 + c4*4);
            v.x += rv.x; v.y += rv.y; v.z += rv.z; v.w += rv.w;
        }
        *(float4*)(Y + r*NC + col0 + c4*4) = v;
    }
}

// ---------------- std-feature chain: 128->64 (act .2) ->32 (act .2) ->2 ----------------
__global__ __launch_bounds__(256) void std_chain(const float* __restrict__ X,
                                                 float* __restrict__ z0out) {
    extern __shared__ float sm[];
    float* Xs  = sm;             // 128*96
    float* w1f = Xs  + 12288;    // 128*64
    float* w1d = w1f + 8192;
    float* z1s = w1d + 8192;     // 64*96
    float* w2f = z1s + 6144;     // 64*32
    float* w2d = w2f + 2048;
    float* z2s = w2d + 2048;     // 32*96
    float* wl  = z2s + 3072;     // 32*2
    int tid = threadIdx.x;
    int col0 = blockIdx.x * 96;
    for (int f = tid; f < 3072; f += 256) {
        int r = f / 24, c4 = f % 24;
        *(float4*)(Xs + r*96 + c4*4) = *(const float4*)(X + r*NC + col0 + c4*4);
    }
    for (int f = tid; f < 2048; f += 256) {
        ((float4*)w1f)[f] = ((const float4*)g_Ws1fT)[f];
        ((float4*)w1d)[f] = ((const float4*)g_Ws1dT)[f];
    }
    for (int f = tid; f < 512; f += 256) {
        ((float4*)w2f)[f] = ((const float4*)g_Ws2fT)[f];
        ((float4*)w2d)[f] = ((const float4*)g_Ws2dT)[f];
    }
    if (tid < 16) ((float4*)wl)[tid] = ((const float4*)g_WslinT)[tid];
    __syncthreads();

    int rg = tid >> 5, cg = tid & 31;    // rg 0..7, cg 0..31
    // stage1: 64 rows, 96 cols; thread tile 8x3
    {
        int r0 = rg*8, c0 = cg*3;
        float af[8][3], ad[8][3];
        #pragma unroll
        for (int i = 0; i < 8; i++) { af[i][0]=af[i][1]=af[i][2]=0.f; ad[i][0]=ad[i][1]=ad[i][2]=0.f; }
        #pragma unroll 4
        for (int k = 0; k < 128; k++) {
            float x0 = Xs[k*96+c0], x1 = Xs[k*96+c0+1], x2 = Xs[k*96+c0+2];
            float4 fa = *(float4*)(w1f + k*64 + r0), fb = *(float4*)(w1f + k*64 + r0 + 4);
            float4 da = *(float4*)(w1d + k*64 + r0), db = *(float4*)(w1d + k*64 + r0 + 4);
            float wf[8] = {fa.x,fa.y,fa.z,fa.w,fb.x,fb.y,fb.z,fb.w};
            float wd[8] = {da.x,da.y,da.z,da.w,db.x,db.y,db.z,db.w};
            #pragma unroll
            for (int i = 0; i < 8; i++) {
                af[i][0] += wf[i]*x0; af[i][1] += wf[i]*x1; af[i][2] += wf[i]*x2;
                ad[i][0] += wd[i]*x0; ad[i][1] += wd[i]*x1; ad[i][2] += wd[i]*x2;
            }
        }
        #pragma unroll
        for (int i = 0; i < 8; i++) {
            float x0=af[i][0],x1=af[i][1],x2=af[i][2];
            float d0=ad[i][0],d1=ad[i][1],d2=ad[i][2];
            float dot = x0*d0 + x1*d1 + x2*d2;
            if (dot < 0.f) {
                float s = 0.8f * dot / (d0*d0 + d1*d1 + d2*d2 + EPSF);
                x0 -= s*d0; x1 -= s*d1; x2 -= s*d2;
            }
            z1s[(r0+i)*96 + c0]   = x0;
            z1s[(r0+i)*96 + c0+1] = x1;
            z1s[(r0+i)*96 + c0+2] = x2;
        }
    }
    __syncthreads();
    // stage2: 32 rows; thread tile 4x3
    {
        int r0 = rg*4, c0 = cg*3;
        float af[4][3], ad[4][3];
        #pragma unroll
        for (int i = 0; i < 4; i++) { af[i][0]=af[i][1]=af[i][2]=0.f; ad[i][0]=ad[i][1]=ad[i][2]=0.f; }
        #pragma unroll 4
        for (int k = 0; k < 64; k++) {
            float x0 = z1s[k*96+c0], x1 = z1s[k*96+c0+1], x2 = z1s[k*96+c0+2];
            float4 fa = *(float4*)(w2f + k*32 + r0);
            float4 da = *(float4*)(w2d + k*32 + r0);
            float wf[4] = {fa.x,fa.y,fa.z,fa.w};
            float wd[4] = {da.x,da.y,da.z,da.w};
            #pragma unroll
            for (int i = 0; i < 4; i++) {
                af[i][0] += wf[i]*x0; af[i][1] += wf[i]*x1; af[i][2] += wf[i]*x2;
                ad[i][0] += wd[i]*x0; ad[i][1] += wd[i]*x1; ad[i][2] += wd[i]*x2;
            }
        }
        #pragma unroll
        for (int i = 0; i < 4; i++) {
            float x0=af[i][0],x1=af[i][1],x2=af[i][2];
            float d0=ad[i][0],d1=ad[i][1],d2=ad[i][2];
            float dot = x0*d0 + x1*d1 + x2*d2;
            if (dot < 0.f) {
                float s = 0.8f * dot / (d0*d0 + d1*d1 + d2*d2 + EPSF);
                x0 -= s*d0; x1 -= s*d1; x2 -= s*d2;
            }
            z2s[(r0+i)*96 + c0]   = x0;
            z2s[(r0+i)*96 + c0+1] = x1;
            z2s[(r0+i)*96 + c0+2] = x2;
        }
    }
    __syncthreads();
    // stage3: 2 rows x 96 cols
    if (tid < 192) {
        int o = tid & 1, c = tid >> 1;
        float a = 0.f;
        #pragma unroll
        for (int k = 0; k < 32; k++) a += wl[k*2 + o] * z2s[k*96 + c];
        z0out[o*NC + col0 + c] = a;
    }
}

// ---------------- frames + x_inv + scatter-add into planes ----------------
__device__ __forceinline__ int cell1(float v) {
    float xy = __fadd_rn(__fdiv_rn(v, 1.101f), 0.5f);
    xy = (xy >= 1.0f) ? (1.0f - 1e-5f) : (xy < 0.f ? 0.f : xy);
    return (int)__fmul_rn(xy, 64.0f);
}

__global__ __launch_bounds__(256) void scatter_kernel(const float* __restrict__ net,
                                                      const float* __restrict__ z0,
                                                      float* __restrict__ out) {
    __shared__ float ns[128*24];
    __shared__ float us[8][9];
    __shared__ int   cs[8][3];
    int tid = threadIdx.x;
    int p0 = blockIdx.x * 8;
    int colb = p0 * 3;
    for (int f = tid; f < 768; f += 256) {
        int r = f / 6, c4 = f % 6;
        *(float4*)(ns + r*24 + c4*4) = *(const float4*)(net + r*NC + colb + c4*4);
    }
    if (tid < 8) {
        int pt = p0 + tid;
        int col = pt * 3;
        float v10=z0[col], v11=z0[col+1], v12=z0[col+2];
        float v20=z0[NC+col], v21=z0[NC+col+1], v22=z0[NC+col+2];
        float n1 = sqrtf(v10*v10 + v11*v11 + v12*v12) + EPSF;
        float u10=v10/n1, u11=v11/n1, u12=v12/n1;
        float pr = v20*u10 + v21*u11 + v22*u12;
        float w0 = v20 - pr*u10, w1 = v21 - pr*u11, w2 = v22 - pr*u12;
        float n2 = sqrtf(w0*w0 + w1*w1 + w2*w2) + EPSF;
        float u20=w0/n2, u21=w1/n2, u22=w2/n2;
        float u30 = u11*u22 - u12*u21;
        float u31 = u12*u20 - u10*u22;
        float u32 = u10*u21 - u11*u20;
        us[tid][0]=u10; us[tid][1]=u11; us[tid][2]=u12;
        us[tid][3]=u20; us[tid][4]=u21; us[tid][5]=u22;
        us[tid][6]=u30; us[tid][7]=u31; us[tid][8]=u32;
        float4 pp = g_p4[pt];
        cs[tid][0] = cell1(pp.x) + 64*cell1(pp.z);
        cs[tid][1] = cell1(pp.x) + 64*cell1(pp.y);
        cs[tid][2] = cell1(pp.y) + 64*cell1(pp.z);
        int b = pt >> 12;
        #pragma unroll
        for (int pl = 0; pl < 3; pl++)
            atomicAdd(&g_cnt[pl*BB*NCELL + b*NCELL + cs[tid][pl]], 1.0f);
    }
    __syncthreads();
    int b = p0 >> 12;
    #pragma unroll
    for (int s = 0; s < 4; s++) {
        int pair = tid + 256*s;
        int ch = pair & 127, q = pair >> 7;
        float n0 = ns[ch*24 + q*3], n1v = ns[ch*24 + q*3 + 1], n2v = ns[ch*24 + q*3 + 2];
        float acc = 0.f;
        #pragma unroll
        for (int k = 0; k < 3; k++) {
            float t = n0*us[q][k*3] + n1v*us[q][k*3+1] + n2v*us[q][k*3+2];
            acc += t*t;
        }
        #pragma unroll
        for (int pl = 0; pl < 3; pl++)
            atomicAdd(&out[((pl*BB + b)*128 + ch)*NCELL + cs[q][pl]], acc);
    }
}

__global__ void zero_kernel(float* __restrict__ p, int n) {
    int i = blockIdx.x*blockDim.x + threadIdx.x;
    if (i < n) p[i] = 0.f;
}

__global__ void finalize_kernel(float* __restrict__ out) {
    int i = blockIdx.x*blockDim.x + threadIdx.x;
    if (i >= 3*BB*128*NCELL) return;
    int cell = i & (NCELL-1);
    int pb = i >> 19;              // 128*4096 = 2^19
    float c = g_cnt[pb*NCELL + cell];
    out[i] = __fdiv_rn(out[i], fmaxf(c, 1.0f));
}

// ---------------- host ----------------
extern "C" void kernel_launch(void* const* d_in, const int* in_sizes, int n_in,
                              void* d_out, int out_size) {
    const float* p     = (const float*)d_in[0];
    const float* Wcp_f = (const float*)d_in[1];
    const float* Wcp_d = (const float*)d_in[2];
    const float* Wfc   = (const float*)d_in[3];
    const float* Wd0s  = (const float*)d_in[4];
    const float* W0s   = (const float*)d_in[5];
    const float* Wd1s  = (const float*)d_in[6];
    const float* W1s   = (const float*)d_in[7];
    const float* Ws1f  = (const float*)d_in[8];
    const float* Ws1d  = (const float*)d_in[9];
    const float* Ws2f  = (const float*)d_in[10];
    const float* Ws2d  = (const float*)d_in[11];
    const float* Wslin = (const float*)d_in[12];
    float* out = (float*)d_out;

    float *bufA, *bufB, *wdT, *wT, *wfcT, *z0, *cnt;
    cudaGetSymbolAddress((void**)&bufA, g_bufA);
    cudaGetSymbolAddress((void**)&bufB, g_bufB);
    cudaGetSymbolAddress((void**)&wdT,  g_WdTs);
    cudaGetSymbolAddress((void**)&wT,   g_WTs);
    cudaGetSymbolAddress((void**)&wfcT, g_WfcT);
    cudaGetSymbolAddress((void**)&z0,   g_z0);
    cudaGetSymbolAddress((void**)&cnt,  g_cnt);

    const int HS_SMEM = (128*TN + 2*128*128) * 4;   // 229376 B
    const int ST_SMEM = 42048 * 4;                  // 168192 B
    cudaFuncSetAttribute(gemm_hs<false,false>, cudaFuncAttributeMaxDynamicSharedMemorySize, HS_SMEM);
    cudaFuncSetAttribute(gemm_hs<true,false>,  cudaFuncAttributeMaxDynamicSharedMemorySize, HS_SMEM);
    cudaFuncSetAttribute(gemm_hs<true,true>,   cudaFuncAttributeMaxDynamicSharedMemorySize, HS_SMEM);
    cudaFuncSetAttribute(std_chain,            cudaFuncAttributeMaxDynamicSharedMemorySize, ST_SMEM);

    prep_points<<<(NPTS+255)/256, 256>>>(p);
    knn_kernel<<<NPTS/128, 128>>>();
    transpose_all<<<dim3(8,26), 256>>>(Wfc, Wd0s, W0s, Wd1s, W1s, Ws1f, Ws1d, Ws2f, Ws2d, Wslin);
    edge_vn<<<NPTS/8, 1024>>>(Wcp_f, Wcp_d, bufA);
    gemm_hs<false,false><<<NC/TN, 256, HS_SMEM>>>(bufA, (const float*)nullptr, wfcT,
                                                  (const float*)nullptr, bufB);
    for (int i = 0; i < 5; i++) {
        gemm_hs<true,false><<<NC/TN, 256, HS_SMEM>>>(bufB, wdT + (2*i)*16384, wT + (2*i)*16384,
                                                     (const float*)nullptr, bufA);
        gemm_hs<true,true><<<NC/TN, 256, HS_SMEM>>>(bufA, wdT + (2*i+1)*16384, wT + (2*i+1)*16384,
                                                    bufB, bufB);
    }
    std_chain<<<NC/96, 256, ST_SMEM>>>(bufB, z0);
    zero_kernel<<<(out_size+255)/256, 256>>>(out, out_size);
    zero_kernel<<<(3*BB*NCELL+255)/256, 256>>>(cnt, 3*BB*NCELL);
    scatter_kernel<<<NPTS/8, 256>>>(bufB, z0, out);
    finalize_kernel<<<(3*BB*128*NCELL+255)/256, 256>>>(out);
}

// round 3
// speedup vs baseline: 1.0025x; 1.0025x over previous
#include <cuda_runtime.h>
#include <cuda_bf16.h>
#include <math.h>
#include <stdint.h>

#define HID   128
#define KNN_K 10
#define NPT   4096
#define BB    4
#define NPTS  (BB*NPT)           // 16384
#define NC    (NPTS*3)           // 49152 columns
#define RESO_ 64
#define NCELL (RESO_*RESO_)      // 4096
#define EPSF  1e-6f
#define TN    192                // gemm column tile

// ---------------- static device scratch ----------------
__device__ __align__(128) float4 g_p4[NPTS];
__device__ __align__(128) int    g_idx[NPTS*KNN_K];
__device__ __align__(128) float  g_cnt[3*BB*NCELL];
__device__ __align__(128) float  g_z0[2*NC];
__device__ __align__(128) float  g_WfcT[HID*HID];
__device__ __align__(128) float  g_WdTs[10*HID*HID];
__device__ __align__(128) float  g_WTs [10*HID*HID];
__device__ __align__(128) float  g_Ws1fT[128*64];
__device__ __align__(128) float  g_Ws1dT[128*64];
__device__ __align__(128) float  g_Ws2fT[64*32];
__device__ __align__(128) float  g_Ws2dT[64*32];
__device__ __align__(128) float  g_WslinT[32*2];
__device__ __align__(128) float  g_bufA[HID*NC];
__device__ __align__(128) float  g_bufB[HID*NC];

// ---------------- prep: pack points + squared norm ----------------
__global__ void prep_points(const float* __restrict__ p) {
    int i = blockIdx.x*blockDim.x + threadIdx.x;
    if (i < NPTS) {
        float x = p[i*3+0], y = p[i*3+1], z = p[i*3+2];
        g_p4[i] = make_float4(x, y, z, x*x + y*y + z*z);
    }
}

// ---------------- transpose all weight matrices: dst[i*O+o] = src[o*I+i] ----------------
__global__ void transpose_all(const float* __restrict__ Wfc,
                              const float* __restrict__ Wd0s, const float* __restrict__ W0s,
                              const float* __restrict__ Wd1s, const float* __restrict__ W1s,
                              const float* __restrict__ Ws1f, const float* __restrict__ Ws1d,
                              const float* __restrict__ Ws2f, const float* __restrict__ Ws2d,
                              const float* __restrict__ Wslin) {
    int m = blockIdx.y;
    const float* src; float* dst; int O, I;
    if (m < 10)      { int i = m >> 1; src = (m & 1) ? (Wd1s + i*16384) : (Wd0s + i*16384);
                       dst = g_WdTs + m*16384; O = 128; I = 128; }
    else if (m < 20) { int h = m - 10; int i = h >> 1; src = (h & 1) ? (W1s + i*16384) : (W0s + i*16384);
                       dst = g_WTs + h*16384; O = 128; I = 128; }
    else if (m == 20){ src = Wfc;   dst = g_WfcT;  O = 128; I = 128; }
    else if (m == 21){ src = Ws1f;  dst = g_Ws1fT; O = 64;  I = 128; }
    else if (m == 22){ src = Ws1d;  dst = g_Ws1dT; O = 64;  I = 128; }
    else if (m == 23){ src = Ws2f;  dst = g_Ws2fT; O = 32;  I = 64; }
    else if (m == 24){ src = Ws2d;  dst = g_Ws2dT; O = 32;  I = 64; }
    else             { src = Wslin; dst = g_WslinT;O = 2;   I = 32; }
    int n = O * I;
    for (int e = blockIdx.x*blockDim.x + threadIdx.x; e < n; e += gridDim.x*blockDim.x) {
        int o = e / I, i = e % I;
        dst[i*O + o] = src[e];
    }
}

// ---------------- brute-force KNN (top-10 of 2*dot - |x|^2 - |y|^2) ----------------
__global__ void knn_kernel() {
    __shared__ float4 cand[128];
    int pt = blockIdx.x*128 + threadIdx.x;       // 4096/128 blocks per batch -> aligned
    int base = (pt >> 12) << 12;
    float4 me = g_p4[pt];
    float v[KNN_K]; int id[KNN_K];
    #pragma unroll
    for (int i = 0; i < KNN_K; i++) { v[i] = -INFINITY; id[i] = 0; }
    for (int t = 0; t < NPT; t += 128) {
        __syncthreads();
        cand[threadIdx.x] = g_p4[base + t + threadIdx.x];
        __syncthreads();
        #pragma unroll 4
        for (int j = 0; j < 128; j++) {
            float4 c = cand[j];
            float nd = 2.0f*(me.x*c.x + me.y*c.y + me.z*c.z) - me.w - c.w;
            if (nd > v[KNN_K-1]) {
                v[KNN_K-1] = nd; id[KNN_K-1] = t + j;
                #pragma unroll
                for (int s = KNN_K-1; s > 0; s--) {
                    if (v[s] > v[s-1]) {
                        float tv = v[s]; v[s] = v[s-1]; v[s-1] = tv;
                        int ti = id[s]; id[s] = id[s-1]; id[s-1] = ti;
                    }
                }
            }
        }
    }
    #pragma unroll
    for (int i = 0; i < KNN_K; i++) g_idx[pt*KNN_K + i] = base + id[i];
}

// ---------------- edge features + first VN layer (slope 0) + mean over k ----------------
// out[o][col], col = pt*3 + coord ; 8 points per block, 1024 threads
__global__ __launch_bounds__(1024) void edge_vn(const float* __restrict__ Wf,
                                                const float* __restrict__ Wd,
                                                float* __restrict__ out) {
    __shared__ float fe[8][KNN_K][9];   // [q][j][i*3+c]: i0=neigh-x, i1=x, i2=cross(neigh,x)
    __shared__ float os[128*24];
    int tid = threadIdx.x;
    int q = tid >> 7, o = tid & 127;
    int p0 = blockIdx.x * 8;
    int pt = p0 + q;
    float4 xm = g_p4[pt];
    if (o < KNN_K) {
        float4 nb = g_p4[g_idx[pt*KNN_K + o]];
        fe[q][o][0] = nb.x - xm.x; fe[q][o][1] = nb.y - xm.y; fe[q][o][2] = nb.z - xm.z;
        fe[q][o][3] = xm.x;        fe[q][o][4] = xm.y;        fe[q][o][5] = xm.z;
        fe[q][o][6] = nb.y*xm.z - nb.z*xm.y;
        fe[q][o][7] = nb.z*xm.x - nb.x*xm.z;
        fe[q][o][8] = nb.x*xm.y - nb.y*xm.x;
    }
    __syncthreads();
    float wf0 = Wf[o*3], wf1 = Wf[o*3+1], wf2 = Wf[o*3+2];
    float wd0 = Wd[o*3], wd1 = Wd[o*3+1], wd2 = Wd[o*3+2];
    float a0 = 0.f, a1 = 0.f, a2 = 0.f;
    #pragma unroll
    for (int j = 0; j < KNN_K; j++) {
        const float* e = fe[q][j];
        float x0 = wf0*e[0] + wf1*e[3] + wf2*e[6];
        float x1 = wf0*e[1] + wf1*e[4] + wf2*e[7];
        float x2 = wf0*e[2] + wf1*e[5] + wf2*e[8];
        float d0 = wd0*e[0] + wd1*e[3] + wd2*e[6];
        float d1 = wd0*e[1] + wd1*e[4] + wd2*e[7];
        float d2 = wd0*e[2] + wd1*e[5] + wd2*e[8];
        float dot = x0*d0 + x1*d1 + x2*d2;
        if (dot < 0.f) {
            float s = dot / (d0*d0 + d1*d1 + d2*d2 + EPSF);
            x0 -= s*d0; x1 -= s*d1; x2 -= s*d2;
        }
        a0 += x0; a1 += x1; a2 += x2;
    }
    os[o*24 + q*3 + 0] = a0 / 10.0f;
    os[o*24 + q*3 + 1] = a1 / 10.0f;
    os[o*24 + q*3 + 2] = a2 / 10.0f;
    __syncthreads();
    for (int f = tid; f < 768; f += 1024) {
        int r = f / 6, c4 = f % 6;
        *(float4*)(out + r*NC + p0*3 + c4*4) = *(float4*)(os + r*24 + c4*4);
    }
}

// ---------------- fused half-step: Y = W * act(X, Wd*X) [+ resid] ----------------
// smem: Xs[128][192] + Ws[128][128] + Wds[128][128] -> 229376 bytes
template<bool ACT, bool RESID>
__global__ __launch_bounds__(256, 1) void gemm_hs(const float* __restrict__ X,
                                                  const float* __restrict__ WdT,
                                                  const float* __restrict__ WT,
                                                  const float* __restrict__ R,
                                                  float* __restrict__ Y) {
    extern __shared__ float sm[];
    float* Xs  = sm;                 // 128*192
    float* Ws  = sm + 128*TN;        // 128*128 [k][m]
    float* Wds = Ws + 128*128;       // 128*128 [k][m]
    const int tid  = threadIdx.x;
    const int col0 = blockIdx.x * TN;

    for (int f = tid; f < 6144; f += 256) {
        int r = f / 48, c4 = f % 48;
        *(float4*)(Xs + r*TN + c4*4) = *(const float4*)(X + r*NC + col0 + c4*4);
    }
    for (int f = tid; f < 4096; f += 256) {
        ((float4*)Ws)[f] = ((const float4*)WT)[f];
        if (ACT) ((float4*)Wds)[f] = ((const float4*)WdT)[f];
    }
    __syncthreads();

    const int rg = tid >> 4, cg = tid & 15;
    const int r0 = rg * 8, c0 = cg * 12;
    float acc[8][12];

    if (ACT) {
        #pragma unroll
        for (int i = 0; i < 8; i++)
            #pragma unroll
            for (int j = 0; j < 12; j++) acc[i][j] = 0.f;
        #pragma unroll 4
        for (int k = 0; k < 128; k++) {
            float4 wa = *(float4*)(Wds + k*128 + r0);
            float4 wb = *(float4*)(Wds + k*128 + r0 + 4);
            float4 xa = *(float4*)(Xs + k*TN + c0);
            float4 xb = *(float4*)(Xs + k*TN + c0 + 4);
            float4 xc = *(float4*)(Xs + k*TN + c0 + 8);
            float w[8]  = {wa.x,wa.y,wa.z,wa.w,wb.x,wb.y,wb.z,wb.w};
            float x[12] = {xa.x,xa.y,xa.z,xa.w,xb.x,xb.y,xb.z,xb.w,xc.x,xc.y,xc.z,xc.w};
            #pragma unroll
            for (int i = 0; i < 8; i++)
                #pragma unroll
                for (int j = 0; j < 12; j++) acc[i][j] += w[i]*x[j];
        }
        __syncthreads();
        // act (slope 0): overwrite Xs with A (thread-private positions only)
        #pragma unroll
        for (int i = 0; i < 8; i++) {
            float* row = Xs + (r0+i)*TN + c0;
            #pragma unroll
            for (int t3 = 0; t3 < 4; t3++) {
                float x0 = row[t3*3], x1 = row[t3*3+1], x2 = row[t3*3+2];
                float d0 = acc[i][t3*3], d1 = acc[i][t3*3+1], d2 = acc[i][t3*3+2];
                float dot = x0*d0 + x1*d1 + x2*d2;
                if (dot < 0.f) {
                    float s = dot / (d0*d0 + d1*d1 + d2*d2 + EPSF);
                    row[t3*3]   = x0 - s*d0;
                    row[t3*3+1] = x1 - s*d1;
                    row[t3*3+2] = x2 - s*d2;
                }
            }
        }
        __syncthreads();
    }

    #pragma unroll
    for (int i = 0; i < 8; i++)
        #pragma unroll
        for (int j = 0; j < 12; j++) acc[i][j] = 0.f;
    #pragma unroll 4
    for (int k = 0; k < 128; k++) {
        float4 wa = *(float4*)(Ws + k*128 + r0);
        float4 wb = *(float4*)(Ws + k*128 + r0 + 4);
        float4 xa = *(float4*)(Xs + k*TN + c0);
        float4 xb = *(float4*)(Xs + k*TN + c0 + 4);
        float4 xc = *(float4*)(Xs + k*TN + c0 + 8);
        float w[8]  = {wa.x,wa.y,wa.z,wa.w,wb.x,wb.y,wb.z,wb.w};
        float x[12] = {xa.x,xa.y,xa.z,xa.w,xb.x,xb.y,xb.z,xb.w,xc.x,xc.y,xc.z,xc.w};
        #pragma unroll
        for (int i = 0; i < 8; i++)
            #pragma unroll
            for (int j = 0; j < 12; j++) acc[i][j] += w[i]*x[j];
    }
    __syncthreads();
    #pragma unroll
    for (int i = 0; i < 8; i++)
        #pragma unroll
        for (int j = 0; j < 12; j++) Xs[(r0+i)*TN + c0 + j] = acc[i][j];
    __syncthreads();
    for (int f = tid; f < 6144; f += 256) {
        int r = f / 48, c4 = f % 48;
        float4 v = *(float4*)(Xs + r*TN + c4*4);
        if (RESID) {
            float4 rv = *(const float4*)(R + r*NC + col0 + c4*4);
            v.x += rv.x; v.y += rv.y; v.z += rv.z; v.w += rv.w;
        }
        *(float4*)(Y + r*NC + col0 + c4*4) = v;
    }
}

// ---------------- std-feature chain: 128->64 (act .2) ->32 (act .2) ->2 ----------------
__global__ __launch_bounds__(256) void std_chain(const float* __restrict__ X,
                                                 float* __restrict__ z0out) {
    extern __shared__ float sm[];
    float* Xs  = sm;             // 128*96
    float* w1f = Xs  + 12288;    // 128*64
    float* w1d = w1f + 8192;
    float* z1s = w1d + 8192;     // 64*96
    float* w2f = z1s + 6144;     // 64*32
    float* w2d = w2f + 2048;
    float* z2s = w2d + 2048;     // 32*96
    float* wl  = z2s + 3072;     // 32*2
    int tid = threadIdx.x;
    int col0 = blockIdx.x * 96;
    for (int f = tid; f < 3072; f += 256) {
        int r = f / 24, c4 = f % 24;
        *(float4*)(Xs + r*96 + c4*4) = *(const float4*)(X + r*NC + col0 + c4*4);
    }
    for (int f = tid; f < 2048; f += 256) {
        ((float4*)w1f)[f] = ((const float4*)g_Ws1fT)[f];
        ((float4*)w1d)[f] = ((const float4*)g_Ws1dT)[f];
    }
    for (int f = tid; f < 512; f += 256) {
        ((float4*)w2f)[f] = ((const float4*)g_Ws2fT)[f];
        ((float4*)w2d)[f] = ((const float4*)g_Ws2dT)[f];
    }
    if (tid < 16) ((float4*)wl)[tid] = ((const float4*)g_WslinT)[tid];
    __syncthreads();

    int rg = tid >> 5, cg = tid & 31;    // rg 0..7, cg 0..31
    // stage1: 64 rows, 96 cols; thread tile 8x3
    {
        int r0 = rg*8, c0 = cg*3;
        float af[8][3], ad[8][3];
        #pragma unroll
        for (int i = 0; i < 8; i++) { af[i][0]=af[i][1]=af[i][2]=0.f; ad[i][0]=ad[i][1]=ad[i][2]=0.f; }
        #pragma unroll 4
        for (int k = 0; k < 128; k++) {
            float x0 = Xs[k*96+c0], x1 = Xs[k*96+c0+1], x2 = Xs[k*96+c0+2];
            float4 fa = *(float4*)(w1f + k*64 + r0), fb = *(float4*)(w1f + k*64 + r0 + 4);
            float4 da = *(float4*)(w1d + k*64 + r0), db = *(float4*)(w1d + k*64 + r0 + 4);
            float wf[8] = {fa.x,fa.y,fa.z,fa.w,fb.x,fb.y,fb.z,fb.w};
            float wd[8] = {da.x,da.y,da.z,da.w,db.x,db.y,db.z,db.w};
            #pragma unroll
            for (int i = 0; i < 8; i++) {
                af[i][0] += wf[i]*x0; af[i][1] += wf[i]*x1; af[i][2] += wf[i]*x2;
                ad[i][0] += wd[i]*x0; ad[i][1] += wd[i]*x1; ad[i][2] += wd[i]*x2;
            }
        }
        #pragma unroll
        for (int i = 0; i < 8; i++) {
            float x0=af[i][0],x1=af[i][1],x2=af[i][2];
            float d0=ad[i][0],d1=ad[i][1],d2=ad[i][2];
            float dot = x0*d0 + x1*d1 + x2*d2;
            if (dot < 0.f) {
                float s = 0.8f * dot / (d0*d0 + d1*d1 + d2*d2 + EPSF);
                x0 -= s*d0; x1 -= s*d1; x2 -= s*d2;
            }
            z1s[(r0+i)*96 + c0]   = x0;
            z1s[(r0+i)*96 + c0+1] = x1;
            z1s[(r0+i)*96 + c0+2] = x2;
        }
    }
    __syncthreads();
    // stage2: 32 rows; thread tile 4x3
    {
        int r0 = rg*4, c0 = cg*3;
        float af[4][3], ad[4][3];
        #pragma unroll
        for (int i = 0; i < 4; i++) { af[i][0]=af[i][1]=af[i][2]=0.f; ad[i][0]=ad[i][1]=ad[i][2]=0.f; }
        #pragma unroll 4
        for (int k = 0; k < 64; k++) {
            float x0 = z1s[k*96+c0], x1 = z1s[k*96+c0+1], x2 = z1s[k*96+c0+2];
            float4 fa = *(float4*)(w2f + k*32 + r0);
            float4 da = *(float4*)(w2d + k*32 + r0);
            float wf[4] = {fa.x,fa.y,fa.z,fa.w};
            float wd[4] = {da.x,da.y,da.z,da.w};
            #pragma unroll
            for (int i = 0; i < 4; i++) {
                af[i][0] += wf[i]*x0; af[i][1] += wf[i]*x1; af[i][2] += wf[i]*x2;
                ad[i][0] += wd[i]*x0; ad[i][1] += wd[i]*x1; ad[i][2] += wd[i]*x2;
            }
        }
        #pragma unroll
        for (int i = 0; i < 4; i++) {
            float x0=af[i][0],x1=af[i][1],x2=af[i][2];
            float d0=ad[i][0],d1=ad[i][1],d2=ad[i][2];
            float dot = x0*d0 + x1*d1 + x2*d2;
            if (dot < 0.f) {
                float s = 0.8f * dot / (d0*d0 + d1*d1 + d2*d2 + EPSF);
                x0 -= s*d0; x1 -= s*d1; x2 -= s*d2;
            }
            z2s[(r0+i)*96 + c0]   = x0;
            z2s[(r0+i)*96 + c0+1] = x1;
            z2s[(r0+i)*96 + c0+2] = x2;
        }
    }
    __syncthreads();
    // stage3: 2 rows x 96 cols
    if (tid < 192) {
        int o = tid & 1, c = tid >> 1;
        float a = 0.f;
        #pragma unroll
        for (int k = 0; k < 32; k++) a += wl[k*2 + o] * z2s[k*96 + c];
        z0out[o*NC + col0 + c] = a;
    }
}

// ---------------- frames + x_inv + scatter-add into planes ----------------
__device__ __forceinline__ int cell1(float v) {
    float xy = __fadd_rn(__fdiv_rn(v, 1.101f), 0.5f);
    xy = (xy >= 1.0f) ? (1.0f - 1e-5f) : (xy < 0.f ? 0.f : xy);
    return (int)__fmul_rn(xy, 64.0f);
}

__global__ __launch_bounds__(256) void scatter_kernel(const float* __restrict__ net,
                                                      const float* __restrict__ z0,
                                                      float* __restrict__ out) {
    __shared__ float ns[128*24];
    __shared__ float us[8][9];
    __shared__ int   cs[8][3];
    int tid = threadIdx.x;
    int p0 = blockIdx.x * 8;
    int colb = p0 * 3;
    for (int f = tid; f < 768; f += 256) {
        int r = f / 6, c4 = f % 6;
        *(float4*)(ns + r*24 + c4*4) = *(const float4*)(net + r*NC + colb + c4*4);
    }
    if (tid < 8) {
        int pt = p0 + tid;
        int col = pt * 3;
        float v10=z0[col], v11=z0[col+1], v12=z0[col+2];
        float v20=z0[NC+col], v21=z0[NC+col+1], v22=z0[NC+col+2];
        float n1 = sqrtf(v10*v10 + v11*v11 + v12*v12) + EPSF;
        float u10=v10/n1, u11=v11/n1, u12=v12/n1;
        float pr = v20*u10 + v21*u11 + v22*u12;
        float w0 = v20 - pr*u10, w1 = v21 - pr*u11, w2 = v22 - pr*u12;
        float n2 = sqrtf(w0*w0 + w1*w1 + w2*w2) + EPSF;
        float u20=w0/n2, u21=w1/n2, u22=w2/n2;
        float u30 = u11*u22 - u12*u21;
        float u31 = u12*u20 - u10*u22;
        float u32 = u10*u21 - u11*u20;
        us[tid][0]=u10; us[tid][1]=u11; us[tid][2]=u12;
        us[tid][3]=u20; us[tid][4]=u21; us[tid][5]=u22;
        us[tid][6]=u30; us[tid][7]=u31; us[tid][8]=u32;
        float4 pp = g_p4[pt];
        cs[tid][0] = cell1(pp.x) + 64*cell1(pp.z);
        cs[tid][1] = cell1(pp.x) + 64*cell1(pp.y);
        cs[tid][2] = cell1(pp.y) + 64*cell1(pp.z);
        int b = pt >> 12;
        #pragma unroll
        for (int pl = 0; pl < 3; pl++)
            atomicAdd(&g_cnt[pl*BB*NCELL + b*NCELL + cs[tid][pl]], 1.0f);
    }
    __syncthreads();
    int b = p0 >> 12;
    #pragma unroll
    for (int s = 0; s < 4; s++) {
        int pair = tid + 256*s;
        int ch = pair & 127, q = pair >> 7;
        float n0 = ns[ch*24 + q*3], n1v = ns[ch*24 + q*3 + 1], n2v = ns[ch*24 + q*3 + 2];
        float acc = 0.f;
        #pragma unroll
        for (int k = 0; k < 3; k++) {
            float t = n0*us[q][k*3] + n1v*us[q][k*3+1] + n2v*us[q][k*3+2];
            acc += t*t;
        }
        #pragma unroll
        for (int pl = 0; pl < 3; pl++)
            atomicAdd(&out[((pl*BB + b)*128 + ch)*NCELL + cs[q][pl]], acc);
    }
}

__global__ void zero_kernel(float* __restrict__ p, int n) {
    int i = blockIdx.x*blockDim.x + threadIdx.x;
    if (i < n) p[i] = 0.f;
}

__global__ void finalize_kernel(float* __restrict__ out) {
    int i = blockIdx.x*blockDim.x + threadIdx.x;
    if (i >= 3*BB*128*NCELL) return;
    int cell = i & (NCELL-1);
    int pb = i >> 19;              // 128*4096 = 2^19
    float c = g_cnt[pb*NCELL + cell];
    out[i] = __fdiv_rn(out[i], fmaxf(c, 1.0f));
}

// ---------------- host ----------------
extern "C" void kernel_launch(void* const* d_in, const int* in_sizes, int n_in,
                              void* d_out, int out_size) {
    const float* p     = (const float*)d_in[0];
    const float* Wcp_f = (const float*)d_in[1];
    const float* Wcp_d = (const float*)d_in[2];
    const float* Wfc   = (const float*)d_in[3];
    const float* Wd0s  = (const float*)d_in[4];
    const float* W0s   = (const float*)d_in[5];
    const float* Wd1s  = (const float*)d_in[6];
    const float* W1s   = (const float*)d_in[7];
    const float* Ws1f  = (const float*)d_in[8];
    const float* Ws1d  = (const float*)d_in[9];
    const float* Ws2f  = (const float*)d_in[10];
    const float* Ws2d  = (const float*)d_in[11];
    const float* Wslin = (const float*)d_in[12];
    float* out = (float*)d_out;

    float *bufA, *bufB, *wdT, *wT, *wfcT, *z0, *cnt;
    cudaGetSymbolAddress((void**)&bufA, g_bufA);
    cudaGetSymbolAddress((void**)&bufB, g_bufB);
    cudaGetSymbolAddress((void**)&wdT,  g_WdTs);
    cudaGetSymbolAddress((void**)&wT,   g_WTs);
    cudaGetSymbolAddress((void**)&wfcT, g_WfcT);
    cudaGetSymbolAddress((void**)&z0,   g_z0);
    cudaGetSymbolAddress((void**)&cnt,  g_cnt);

    const int HS_SMEM = (128*TN + 2*128*128) * 4;   // 229376 B
    const int ST_SMEM = 42048 * 4;                  // 168192 B
    cudaFuncSetAttribute(gemm_hs<false,false>, cudaFuncAttributeMaxDynamicSharedMemorySize, HS_SMEM);
    cudaFuncSetAttribute(gemm_hs<true,false>,  cudaFuncAttributeMaxDynamicSharedMemorySize, HS_SMEM);
    cudaFuncSetAttribute(gemm_hs<true,true>,   cudaFuncAttributeMaxDynamicSharedMemorySize, HS_SMEM);
    cudaFuncSetAttribute(std_chain,            cudaFuncAttributeMaxDynamicSharedMemorySize, ST_SMEM);

    prep_points<<<(NPTS+255)/256, 256>>>(p);
    knn_kernel<<<NPTS/128, 128>>>();
    transpose_all<<<dim3(8,26), 256>>>(Wfc, Wd0s, W0s, Wd1s, W1s, Ws1f, Ws1d, Ws2f, Ws2d, Wslin);
    edge_vn<<<NPTS/8, 1024>>>(Wcp_f, Wcp_d, bufA);
    gemm_hs<false,false><<<NC/TN, 256, HS_SMEM>>>(bufA, (const float*)nullptr, wfcT,
                                                  (const float*)nullptr, bufB);
    for (int i = 0; i < 5; i++) {
        gemm_hs<true,false><<<NC/TN, 256, HS_SMEM>>>(bufB, wdT + (2*i)*16384, wT + (2*i)*16384,
                                                     (const float*)nullptr, bufA);
        gemm_hs<true,true><<<NC/TN, 256, HS_SMEM>>>(bufA, wdT + (2*i+1)*16384, wT + (2*i+1)*16384,
                                                    bufB, bufB);
    }
    std_chain<<<NC/96, 256, ST_SMEM>>>(bufB, z0);
    zero_kernel<<<(out_size+255)/256, 256>>>(out, out_size);
    zero_kernel<<<(3*BB*NCELL+255)/256, 256>>>(cnt, 3*BB*NCELL);
    scatter_kernel<<<NPTS/8, 256>>>(bufB, z0, out);
    finalize_kernel<<<(3*BB*128*NCELL+255)/256, 256>>>(out);
}

// round 4
// speedup vs baseline: 1.0044x; 1.0018x over previous
#include <cuda_runtime.h>
#include <cuda_bf16.h>
#include <math.h>
#include <stdint.h>

#define HID   128
#define KNN_K 10
#define NPT   4096
#define BB    4
#define NPTS  (BB*NPT)           // 16384
#define NC    (NPTS*3)           // 49152 columns
#define RESO_ 64
#define NCELL (RESO_*RESO_)      // 4096
#define EPSF  1e-6f
#define TN    192                // gemm column tile

// ---------------- static device scratch ----------------
__device__ __align__(128) float4 g_p4[NPTS];
__device__ __align__(128) int    g_idx[NPTS*KNN_K];
__device__ __align__(128) float  g_cnt[3*BB*NCELL];
__device__ __align__(128) float  g_z0[2*NC];
__device__ __align__(128) float  g_WfcT[HID*HID];
__device__ __align__(128) float  g_WdTs[10*HID*HID];
__device__ __align__(128) float  g_WTs [10*HID*HID];
__device__ __align__(128) float  g_Ws1fT[128*64];
__device__ __align__(128) float  g_Ws1dT[128*64];
__device__ __align__(128) float  g_Ws2fT[64*32];
__device__ __align__(128) float  g_Ws2dT[64*32];
__device__ __align__(128) float  g_WslinT[32*2];
__device__ __align__(128) float  g_bufA[HID*NC];
__device__ __align__(128) float  g_bufB[HID*NC];

// ---------------- prep: pack points + squared norm ----------------
__global__ void prep_points(const float* __restrict__ p) {
    int i = blockIdx.x*blockDim.x + threadIdx.x;
    if (i < NPTS) {
        float x = p[i*3+0], y = p[i*3+1], z = p[i*3+2];
        g_p4[i] = make_float4(x, y, z, x*x + y*y + z*z);
    }
}

// ---------------- transpose all weight matrices: dst[i*O+o] = src[o*I+i] ----------------
__global__ void transpose_all(const float* __restrict__ Wfc,
                              const float* __restrict__ Wd0s, const float* __restrict__ W0s,
                              const float* __restrict__ Wd1s, const float* __restrict__ W1s,
                              const float* __restrict__ Ws1f, const float* __restrict__ Ws1d,
                              const float* __restrict__ Ws2f, const float* __restrict__ Ws2d,
                              const float* __restrict__ Wslin) {
    int m = blockIdx.y;
    const float* src; float* dst; int O, I;
    if (m < 10)      { int i = m >> 1; src = (m & 1) ? (Wd1s + i*16384) : (Wd0s + i*16384);
                       dst = g_WdTs + m*16384; O = 128; I = 128; }
    else if (m < 20) { int h = m - 10; int i = h >> 1; src = (h & 1) ? (W1s + i*16384) : (W0s + i*16384);
                       dst = g_WTs + h*16384; O = 128; I = 128; }
    else if (m == 20){ src = Wfc;   dst = g_WfcT;  O = 128; I = 128; }
    else if (m == 21){ src = Ws1f;  dst = g_Ws1fT; O = 64;  I = 128; }
    else if (m == 22){ src = Ws1d;  dst = g_Ws1dT; O = 64;  I = 128; }
    else if (m == 23){ src = Ws2f;  dst = g_Ws2fT; O = 32;  I = 64; }
    else if (m == 24){ src = Ws2d;  dst = g_Ws2dT; O = 32;  I = 64; }
    else             { src = Wslin; dst = g_WslinT;O = 2;   I = 32; }
    int n = O * I;
    for (int e = blockIdx.x*blockDim.x + threadIdx.x; e < n; e += gridDim.x*blockDim.x) {
        int o = e / I, i = e % I;
        dst[i*O + o] = src[e];
    }
}

// ---------------- brute-force KNN (top-10 of 2*dot - |x|^2 - |y|^2) ----------------
__global__ void knn_kernel() {
    __shared__ float4 cand[128];
    int pt = blockIdx.x*128 + threadIdx.x;       // 4096/128 blocks per batch -> aligned
    int base = (pt >> 12) << 12;
    float4 me = g_p4[pt];
    float v[KNN_K]; int id[KNN_K];
    #pragma unroll
    for (int i = 0; i < KNN_K; i++) { v[i] = -INFINITY; id[i] = 0; }
    for (int t = 0; t < NPT; t += 128) {
        __syncthreads();
        cand[threadIdx.x] = g_p4[base + t + threadIdx.x];
        __syncthreads();
        #pragma unroll 4
        for (int j = 0; j < 128; j++) {
            float4 c = cand[j];
            float nd = 2.0f*(me.x*c.x + me.y*c.y + me.z*c.z) - me.w - c.w;
            if (nd > v[KNN_K-1]) {
                v[KNN_K-1] = nd; id[KNN_K-1] = t + j;
                #pragma unroll
                for (int s = KNN_K-1; s > 0; s--) {
                    if (v[s] > v[s-1]) {
                        float tv = v[s]; v[s] = v[s-1]; v[s-1] = tv;
                        int ti = id[s]; id[s] = id[s-1]; id[s-1] = ti;
                    }
                }
            }
        }
    }
    #pragma unroll
    for (int i = 0; i < KNN_K; i++) g_idx[pt*KNN_K + i] = base + id[i];
}

// ---------------- edge features + first VN layer (slope 0) + mean over k ----------------
// out[o][col], col = pt*3 + coord ; 8 points per block, 1024 threads
__global__ __launch_bounds__(1024) void edge_vn(const float* __restrict__ Wf,
                                                const float* __restrict__ Wd,
                                                float* __restrict__ out) {
    __shared__ float fe[8][KNN_K][9];   // [q][j][i*3+c]: i0=neigh-x, i1=x, i2=cross(neigh,x)
    __shared__ float os[128*24];
    int tid = threadIdx.x;
    int q = tid >> 7, o = tid & 127;
    int p0 = blockIdx.x * 8;
    int pt = p0 + q;
    float4 xm = g_p4[pt];
    if (o < KNN_K) {
        float4 nb = g_p4[g_idx[pt*KNN_K + o]];
        fe[q][o][0] = nb.x - xm.x; fe[q][o][1] = nb.y - xm.y; fe[q][o][2] = nb.z - xm.z;
        fe[q][o][3] = xm.x;        fe[q][o][4] = xm.y;        fe[q][o][5] = xm.z;
        fe[q][o][6] = nb.y*xm.z - nb.z*xm.y;
        fe[q][o][7] = nb.z*xm.x - nb.x*xm.z;
        fe[q][o][8] = nb.x*xm.y - nb.y*xm.x;
    }
    __syncthreads();
    float wf0 = Wf[o*3], wf1 = Wf[o*3+1], wf2 = Wf[o*3+2];
    float wd0 = Wd[o*3], wd1 = Wd[o*3+1], wd2 = Wd[o*3+2];
    float a0 = 0.f, a1 = 0.f, a2 = 0.f;
    #pragma unroll
    for (int j = 0; j < KNN_K; j++) {
        const float* e = fe[q][j];
        float x0 = wf0*e[0] + wf1*e[3] + wf2*e[6];
        float x1 = wf0*e[1] + wf1*e[4] + wf2*e[7];
        float x2 = wf0*e[2] + wf1*e[5] + wf2*e[8];
        float d0 = wd0*e[0] + wd1*e[3] + wd2*e[6];
        float d1 = wd0*e[1] + wd1*e[4] + wd2*e[7];
        float d2 = wd0*e[2] + wd1*e[5] + wd2*e[8];
        float dot = x0*d0 + x1*d1 + x2*d2;
        if (dot < 0.f) {
            float s = dot / (d0*d0 + d1*d1 + d2*d2 + EPSF);
            x0 -= s*d0; x1 -= s*d1; x2 -= s*d2;
        }
        a0 += x0; a1 += x1; a2 += x2;
    }
    os[o*24 + q*3 + 0] = a0 / 10.0f;
    os[o*24 + q*3 + 1] = a1 / 10.0f;
    os[o*24 + q*3 + 2] = a2 / 10.0f;
    __syncthreads();
    for (int f = tid; f < 768; f += 1024) {
        int r = f / 6, c4 = f % 6;
        *(float4*)(out + r*NC + p0*3 + c4*4) = *(float4*)(os + r*24 + c4*4);
    }
}

// ---------------- fused half-step: Y = W * act(X, Wd*X) [+ resid] ----------------
// smem: Xs[128][192] + Ws[128][128] + Wds[128][128] -> 229376 bytes
template<bool ACT, bool RESID>
__global__ __launch_bounds__(256, 1) void gemm_hs(const float* __restrict__ X,
                                                  const float* __restrict__ WdT,
                                                  const float* __restrict__ WT,
                                                  const float* __restrict__ R,
                                                  float* __restrict__ Y) {
    extern __shared__ float sm[];
    float* Xs  = sm;                 // 128*192
    float* Ws  = sm + 128*TN;        // 128*128 [k][m]
    float* Wds = Ws + 128*128;       // 128*128 [k][m]
    const int tid  = threadIdx.x;
    const int col0 = blockIdx.x * TN;

    for (int f = tid; f < 6144; f += 256) {
        int r = f / 48, c4 = f % 48;
        *(float4*)(Xs + r*TN + c4*4) = *(const float4*)(X + r*NC + col0 + c4*4);
    }
    for (int f = tid; f < 4096; f += 256) {
        ((float4*)Ws)[f] = ((const float4*)WT)[f];
        if (ACT) ((float4*)Wds)[f] = ((const float4*)WdT)[f];
    }
    __syncthreads();

    const int rg = tid >> 4, cg = tid & 15;
    const int r0 = rg * 8, c0 = cg * 12;
    float acc[8][12];

    if (ACT) {
        #pragma unroll
        for (int i = 0; i < 8; i++)
            #pragma unroll
            for (int j = 0; j < 12; j++) acc[i][j] = 0.f;
        #pragma unroll 4
        for (int k = 0; k < 128; k++) {
            float4 wa = *(float4*)(Wds + k*128 + r0);
            float4 wb = *(float4*)(Wds + k*128 + r0 + 4);
            float4 xa = *(float4*)(Xs + k*TN + c0);
            float4 xb = *(float4*)(Xs + k*TN + c0 + 4);
            float4 xc = *(float4*)(Xs + k*TN + c0 + 8);
            float w[8]  = {wa.x,wa.y,wa.z,wa.w,wb.x,wb.y,wb.z,wb.w};
            float x[12] = {xa.x,xa.y,xa.z,xa.w,xb.x,xb.y,xb.z,xb.w,xc.x,xc.y,xc.z,xc.w};
            #pragma unroll
            for (int i = 0; i < 8; i++)
                #pragma unroll
                for (int j = 0; j < 12; j++) acc[i][j] += w[i]*x[j];
        }
        __syncthreads();
        // act (slope 0): overwrite Xs with A (thread-private positions only)
        #pragma unroll
        for (int i = 0; i < 8; i++) {
            float* row = Xs + (r0+i)*TN + c0;
            #pragma unroll
            for (int t3 = 0; t3 < 4; t3++) {
                float x0 = row[t3*3], x1 = row[t3*3+1], x2 = row[t3*3+2];
                float d0 = acc[i][t3*3], d1 = acc[i][t3*3+1], d2 = acc[i][t3*3+2];
                float dot = x0*d0 + x1*d1 + x2*d2;
                if (dot < 0.f) {
                    float s = dot / (d0*d0 + d1*d1 + d2*d2 + EPSF);
                    row[t3*3]   = x0 - s*d0;
                    row[t3*3+1] = x1 - s*d1;
                    row[t3*3+2] = x2 - s*d2;
                }
            }
        }
        __syncthreads();
    }

    #pragma unroll
    for (int i = 0; i < 8; i++)
        #pragma unroll
        for (int j = 0; j < 12; j++) acc[i][j] = 0.f;
    #pragma unroll 4
    for (int k = 0; k < 128; k++) {
        float4 wa = *(float4*)(Ws + k*128 + r0);
        float4 wb = *(float4*)(Ws + k*128 + r0 + 4);
        float4 xa = *(float4*)(Xs + k*TN + c0);
        float4 xb = *(float4*)(Xs + k*TN + c0 + 4);
        float4 xc = *(float4*)(Xs + k*TN + c0 + 8);
        float w[8]  = {wa.x,wa.y,wa.z,wa.w,wb.x,wb.y,wb.z,wb.w};
        float x[12] = {xa.x,xa.y,xa.z,xa.w,xb.x,xb.y,xb.z,xb.w,xc.x,xc.y,xc.z,xc.w};
        #pragma unroll
        for (int i = 0; i < 8; i++)
            #pragma unroll
            for (int j = 0; j < 12; j++) acc[i][j] += w[i]*x[j];
    }
    __syncthreads();
    #pragma unroll
    for (int i = 0; i < 8; i++)
        #pragma unroll
        for (int j = 0; j < 12; j++) Xs[(r0+i)*TN + c0 + j] = acc[i][j];
    __syncthreads();
    for (int f = tid; f < 6144; f += 256) {
        int r = f / 48, c4 = f % 48;
        float4 v = *(float4*)(Xs + r*TN + c4*4);
        if (RESID) {
            float4 rv = *(const float4*)(R + r*NC + col0 + c4*4);
            v.x += rv.x; v.y += rv.y; v.z += rv.z; v.w += rv.w;
        }
        *(float4*)(Y + r*NC + col0 + c4*4) = v;
    }
}

// ---------------- std-feature chain: 128->64 (act .2) ->32 (act .2) ->2 ----------------
__global__ __launch_bounds__(256) void std_chain(const float* __restrict__ X,
                                                 float* __restrict__ z0out) {
    extern __shared__ float sm[];
    float* Xs  = sm;             // 128*96
    float* w1f = Xs  + 12288;    // 128*64
    float* w1d = w1f + 8192;
    float* z1s = w1d + 8192;     // 64*96
    float* w2f = z1s + 6144;     // 64*32
    float* w2d = w2f + 2048;
    float* z2s = w2d + 2048;     // 32*96
    float* wl  = z2s + 3072;     // 32*2
    int tid = threadIdx.x;
    int col0 = blockIdx.x * 96;
    for (int f = tid; f < 3072; f += 256) {
        int r = f / 24, c4 = f % 24;
        *(float4*)(Xs + r*96 + c4*4) = *(const float4*)(X + r*NC + col0 + c4*4);
    }
    for (int f = tid; f < 2048; f += 256) {
        ((float4*)w1f)[f] = ((const float4*)g_Ws1fT)[f];
        ((float4*)w1d)[f] = ((const float4*)g_Ws1dT)[f];
    }
    for (int f = tid; f < 512; f += 256) {
        ((float4*)w2f)[f] = ((const float4*)g_Ws2fT)[f];
        ((float4*)w2d)[f] = ((const float4*)g_Ws2dT)[f];
    }
    if (tid < 16) ((float4*)wl)[tid] = ((const float4*)g_WslinT)[tid];
    __syncthreads();

    int rg = tid >> 5, cg = tid & 31;    // rg 0..7, cg 0..31
    // stage1: 64 rows, 96 cols; thread tile 8x3
    {
        int r0 = rg*8, c0 = cg*3;
        float af[8][3], ad[8][3];
        #pragma unroll
        for (int i = 0; i < 8; i++) { af[i][0]=af[i][1]=af[i][2]=0.f; ad[i][0]=ad[i][1]=ad[i][2]=0.f; }
        #pragma unroll 4
        for (int k = 0; k < 128; k++) {
            float x0 = Xs[k*96+c0], x1 = Xs[k*96+c0+1], x2 = Xs[k*96+c0+2];
            float4 fa = *(float4*)(w1f + k*64 + r0), fb = *(float4*)(w1f + k*64 + r0 + 4);
            float4 da = *(float4*)(w1d + k*64 + r0), db = *(float4*)(w1d + k*64 + r0 + 4);
            float wf[8] = {fa.x,fa.y,fa.z,fa.w,fb.x,fb.y,fb.z,fb.w};
            float wd[8] = {da.x,da.y,da.z,da.w,db.x,db.y,db.z,db.w};
            #pragma unroll
            for (int i = 0; i < 8; i++) {
                af[i][0] += wf[i]*x0; af[i][1] += wf[i]*x1; af[i][2] += wf[i]*x2;
                ad[i][0] += wd[i]*x0; ad[i][1] += wd[i]*x1; ad[i][2] += wd[i]*x2;
            }
        }
        #pragma unroll
        for (int i = 0; i < 8; i++) {
            float x0=af[i][0],x1=af[i][1],x2=af[i][2];
            float d0=ad[i][0],d1=ad[i][1],d2=ad[i][2];
            float dot = x0*d0 + x1*d1 + x2*d2;
            if (dot < 0.f) {
                float s = 0.8f * dot / (d0*d0 + d1*d1 + d2*d2 + EPSF);
                x0 -= s*d0; x1 -= s*d1; x2 -= s*d2;
            }
            z1s[(r0+i)*96 + c0]   = x0;
            z1s[(r0+i)*96 + c0+1] = x1;
            z1s[(r0+i)*96 + c0+2] = x2;
        }
    }
    __syncthreads();
    // stage2: 32 rows; thread tile 4x3
    {
        int r0 = rg*4, c0 = cg*3;
        float af[4][3], ad[4][3];
        #pragma unroll
        for (int i = 0; i < 4; i++) { af[i][0]=af[i][1]=af[i][2]=0.f; ad[i][0]=ad[i][1]=ad[i][2]=0.f; }
        #pragma unroll 4
        for (int k = 0; k < 64; k++) {
            float x0 = z1s[k*96+c0], x1 = z1s[k*96+c0+1], x2 = z1s[k*96+c0+2];
            float4 fa = *(float4*)(w2f + k*32 + r0);
            float4 da = *(float4*)(w2d + k*32 + r0);
            float wf[4] = {fa.x,fa.y,fa.z,fa.w};
            float wd[4] = {da.x,da.y,da.z,da.w};
            #pragma unroll
            for (int i = 0; i < 4; i++) {
                af[i][0] += wf[i]*x0; af[i][1] += wf[i]*x1; af[i][2] += wf[i]*x2;
                ad[i][0] += wd[i]*x0; ad[i][1] += wd[i]*x1; ad[i][2] += wd[i]*x2;
            }
        }
        #pragma unroll
        for (int i = 0; i < 4; i++) {
            float x0=af[i][0],x1=af[i][1],x2=af[i][2];
            float d0=ad[i][0],d1=ad[i][1],d2=ad[i][2];
            float dot = x0*d0 + x1*d1 + x2*d2;
            if (dot < 0.f) {
                float s = 0.8f * dot / (d0*d0 + d1*d1 + d2*d2 + EPSF);
                x0 -= s*d0; x1 -= s*d1; x2 -= s*d2;
            }
            z2s[(r0+i)*96 + c0]   = x0;
            z2s[(r0+i)*96 + c0+1] = x1;
            z2s[(r0+i)*96 + c0+2] = x2;
        }
    }
    __syncthreads();
    // stage3: 2 rows x 96 cols
    if (tid < 192) {
        int o = tid & 1, c = tid >> 1;
        float a = 0.f;
        #pragma unroll
        for (int k = 0; k < 32; k++) a += wl[k*2 + o] * z2s[k*96 + c];
        z0out[o*NC + col0 + c] = a;
    }
}

// ---------------- frames + x_inv + scatter-add into planes ----------------
__device__ __forceinline__ int cell1(float v) {
    float xy = __fadd_rn(__fdiv_rn(v, 1.101f), 0.5f);
    xy = (xy >= 1.0f) ? (1.0f - 1e-5f) : (xy < 0.f ? 0.f : xy);
    return (int)__fmul_rn(xy, 64.0f);
}

__global__ __launch_bounds__(256) void scatter_kernel(const float* __restrict__ net,
                                                      const float* __restrict__ z0,
                                                      float* __restrict__ out) {
    __shared__ float ns[128*24];
    __shared__ float us[8][9];
    __shared__ int   cs[8][3];
    int tid = threadIdx.x;
    int p0 = blockIdx.x * 8;
    int colb = p0 * 3;
    for (int f = tid; f < 768; f += 256) {
        int r = f / 6, c4 = f % 6;
        *(float4*)(ns + r*24 + c4*4) = *(const float4*)(net + r*NC + colb + c4*4);
    }
    if (tid < 8) {
        int pt = p0 + tid;
        int col = pt * 3;
        float v10=z0[col], v11=z0[col+1], v12=z0[col+2];
        float v20=z0[NC+col], v21=z0[NC+col+1], v22=z0[NC+col+2];
        float n1 = sqrtf(v10*v10 + v11*v11 + v12*v12) + EPSF;
        float u10=v10/n1, u11=v11/n1, u12=v12/n1;
        float pr = v20*u10 + v21*u11 + v22*u12;
        float w0 = v20 - pr*u10, w1 = v21 - pr*u11, w2 = v22 - pr*u12;
        float n2 = sqrtf(w0*w0 + w1*w1 + w2*w2) + EPSF;
        float u20=w0/n2, u21=w1/n2, u22=w2/n2;
        float u30 = u11*u22 - u12*u21;
        float u31 = u12*u20 - u10*u22;
        float u32 = u10*u21 - u11*u20;
        us[tid][0]=u10; us[tid][1]=u11; us[tid][2]=u12;
        us[tid][3]=u20; us[tid][4]=u21; us[tid][5]=u22;
        us[tid][6]=u30; us[tid][7]=u31; us[tid][8]=u32;
        float4 pp = g_p4[pt];
        cs[tid][0] = cell1(pp.x) + 64*cell1(pp.z);
        cs[tid][1] = cell1(pp.x) + 64*cell1(pp.y);
        cs[tid][2] = cell1(pp.y) + 64*cell1(pp.z);
        int b = pt >> 12;
        #pragma unroll
        for (int pl = 0; pl < 3; pl++)
            atomicAdd(&g_cnt[pl*BB*NCELL + b*NCELL + cs[tid][pl]], 1.0f);
    }
    __syncthreads();
    int b = p0 >> 12;
    #pragma unroll
    for (int s = 0; s < 4; s++) {
        int pair = tid + 256*s;
        int ch = pair & 127, q = pair >> 7;
        float n0 = ns[ch*24 + q*3], n1v = ns[ch*24 + q*3 + 1], n2v = ns[ch*24 + q*3 + 2];
        float acc = 0.f;
        #pragma unroll
        for (int k = 0; k < 3; k++) {
            float t = n0*us[q][k*3] + n1v*us[q][k*3+1] + n2v*us[q][k*3+2];
            acc += t*t;
        }
        #pragma unroll
        for (int pl = 0; pl < 3; pl++)
            atomicAdd(&out[((pl*BB + b)*128 + ch)*NCELL + cs[q][pl]], acc);
    }
}

__global__ void zero_kernel(float* __restrict__ p, int n) {
    int i = blockIdx.x*blockDim.x + threadIdx.x;
    if (i < n) p[i] = 0.f;
}

__global__ void finalize_kernel(float* __restrict__ out) {
    int i = blockIdx.x*blockDim.x + threadIdx.x;
    if (i >= 3*BB*128*NCELL) return;
    int cell = i & (NCELL-1);
    int pb = i >> 19;              // 128*4096 = 2^19
    float c = g_cnt[pb*NCELL + cell];
    out[i] = __fdiv_rn(out[i], fmaxf(c, 1.0f));
}

// ---------------- host ----------------
extern "C" void kernel_launch(void* const* d_in, const int* in_sizes, int n_in,
                              void* d_out, int out_size) {
    const float* p     = (const float*)d_in[0];
    const float* Wcp_f = (const float*)d_in[1];
    const float* Wcp_d = (const float*)d_in[2];
    const float* Wfc   = (const float*)d_in[3];
    const float* Wd0s  = (const float*)d_in[4];
    const float* W0s   = (const float*)d_in[5];
    const float* Wd1s  = (const float*)d_in[6];
    const float* W1s   = (const float*)d_in[7];
    const float* Ws1f  = (const float*)d_in[8];
    const float* Ws1d  = (const float*)d_in[9];
    const float* Ws2f  = (const float*)d_in[10];
    const float* Ws2d  = (const float*)d_in[11];
    const float* Wslin = (const float*)d_in[12];
    float* out = (float*)d_out;

    float *bufA, *bufB, *wdT, *wT, *wfcT, *z0, *cnt;
    cudaGetSymbolAddress((void**)&bufA, g_bufA);
    cudaGetSymbolAddress((void**)&bufB, g_bufB);
    cudaGetSymbolAddress((void**)&wdT,  g_WdTs);
    cudaGetSymbolAddress((void**)&wT,   g_WTs);
    cudaGetSymbolAddress((void**)&wfcT, g_WfcT);
    cudaGetSymbolAddress((void**)&z0,   g_z0);
    cudaGetSymbolAddress((void**)&cnt,  g_cnt);

    const int HS_SMEM = (128*TN + 2*128*128) * 4;   // 229376 B
    const int ST_SMEM = 42048 * 4;                  // 168192 B
    cudaFuncSetAttribute(gemm_hs<false,false>, cudaFuncAttributeMaxDynamicSharedMemorySize, HS_SMEM);
    cudaFuncSetAttribute(gemm_hs<true,false>,  cudaFuncAttributeMaxDynamicSharedMemorySize, HS_SMEM);
    cudaFuncSetAttribute(gemm_hs<true,true>,   cudaFuncAttributeMaxDynamicSharedMemorySize, HS_SMEM);
    cudaFuncSetAttribute(std_chain,            cudaFuncAttributeMaxDynamicSharedMemorySize, ST_SMEM);

    prep_points<<<(NPTS+255)/256, 256>>>(p);
    knn_kernel<<<NPTS/128, 128>>>();
    transpose_all<<<dim3(8,26), 256>>>(Wfc, Wd0s, W0s, Wd1s, W1s, Ws1f, Ws1d, Ws2f, Ws2d, Wslin);
    edge_vn<<<NPTS/8, 1024>>>(Wcp_f, Wcp_d, bufA);
    gemm_hs<false,false><<<NC/TN, 256, HS_SMEM>>>(bufA, (const float*)nullptr, wfcT,
                                                  (const float*)nullptr, bufB);
    for (int i = 0; i < 5; i++) {
        gemm_hs<true,false><<<NC/TN, 256, HS_SMEM>>>(bufB, wdT + (2*i)*16384, wT + (2*i)*16384,
                                                     (const float*)nullptr, bufA);
        gemm_hs<true,true><<<NC/TN, 256, HS_SMEM>>>(bufA, wdT + (2*i+1)*16384, wT + (2*i+1)*16384,
                                                    bufB, bufB);
    }
    std_chain<<<NC/96, 256, ST_SMEM>>>(bufB, z0);
    zero_kernel<<<(out_size+255)/256, 256>>>(out, out_size);
    zero_kernel<<<(3*BB*NCELL+255)/256, 256>>>(cnt, 3*BB*NCELL);
    scatter_kernel<<<NPTS/8, 256>>>(bufB, z0, out);
    finalize_kernel<<<(3*BB*128*NCELL+255)/256, 256>>>(out);
}